// round 5
// baseline (speedup 1.0000x reference)
#include <cuda_runtime.h>

#define EPSF 1.1920929e-07f
typedef unsigned long long ull;

constexpr int TILE  = 64;
constexpr int HALO  = 10;
constexpr int NTOK  = 76;          // TILE + HALO + 2 (quad multiple)
constexpr int NGATE = 74;          // TILE + HALO
constexpr int ESTR  = 76;          // emb_sh token stride
constexpr int KSTR  = 132;         // 16B-aligned rows
constexpr int VSTR  = 36;

// shared layout (float offsets)
constexpr int SM_EMB = 0;                     // [32][76]
constexpr int SM_K   = SM_EMB + 32 * NTOK;    // [76][132] keys
constexpr int SM_V   = SM_K + NTOK * KSTR;    // [76][36]  values
constexpr int SM_G   = SM_V + NTOK * VSTR;    // [74][4][2] (grr, gate)
constexpr int SM_NN  = SM_G + NGATE * 8;      // [128] n1*n2
constexpr int SM_FLOATS = SM_NN + 128;        // 15920 floats = 63680 B

__device__ __forceinline__ ull fma2(ull a, ull b, ull c) {
    ull d; asm("fma.rn.f32x2 %0, %1, %2, %3;" : "=l"(d) : "l"(a), "l"(b), "l"(c)); return d;
}
__device__ __forceinline__ ull mul2(ull a, ull b) {
    ull d; asm("mul.rn.f32x2 %0, %1, %2;" : "=l"(d) : "l"(a), "l"(b)); return d;
}
__device__ __forceinline__ ull add2(ull a, ull b) {
    ull d; asm("add.rn.f32x2 %0, %1, %2;" : "=l"(d) : "l"(a), "l"(b)); return d;
}
__device__ __forceinline__ ull pack2(float x, float y) {
    ull r; asm("mov.b64 %0, {%1, %2};" : "=l"(r) : "f"(x), "f"(y)); return r;
}
__device__ __forceinline__ float lo2(ull a) { float2 f = *(float2*)&a; return f.x; }
__device__ __forceinline__ float hi2(ull a) { float2 f = *(float2*)&a; return f.y; }

__global__ void __launch_bounds__(320, 3)
engram_kernel(const float* __restrict__ emb, const float* __restrict__ hid,
              const float* __restrict__ Wv,  const float* __restrict__ bv,
              const float* __restrict__ Wk,  const float* __restrict__ bk,
              const float* __restrict__ n1w, const float* __restrict__ n2w,
              const float* __restrict__ cnw, const float* __restrict__ cvw,
              float* __restrict__ out, int T)
{
    extern __shared__ float sm[];
    const int tid        = threadIdx.x;
    const int b          = blockIdx.y;
    const int tile_start = blockIdx.x * TILE;
    const long base_tok  = (long)b * T + tile_start;

    // Phase-B identity (computed early for prefetch)
    const int bg   = (tid < 296) ? tid / 74 : 0;
    const int btok = (tid < 296) ? tid - bg * 74 : 0;
    const int bgt  = tile_start - HALO + btok;
    const float* hrow = hid + (((base_tok - HALO + btok) << 2) + bg) * 32;
    if (tid < 296 && bgt >= 0)
        asm volatile("prefetch.global.L2 [%0];" :: "l"(hrow));

    // ---- stage emb transposed + nn ----
    for (int idx = tid; idx < 32 * NTOK; idx += 320) {
        int tok = idx >> 5, d = idx & 31;
        int gt  = tile_start - HALO + tok;
        float val = 0.f;
        if (tok < TILE + HALO && gt >= 0)
            val = emb[(base_tok - HALO + tok) * 32 + d];
        sm[SM_EMB + d * ESTR + tok] = val;
    }
    if (tid < 128) sm[SM_NN + tid] = n1w[tid] * n2w[tid];

    // ---- per-thread projection weights: (channel, d-half) split ----
    const int ch = tid >> 1;      // 0..159
    const int dh = tid & 1;       // d-half: 0 -> d 0..15, 1 -> d 16..31
    ull w2[16], bias2 = 0ull;
    {
        const float* wrow = (ch < 128) ? (Wk + ch * 32) : (Wv + (ch - 128) * 32);
        wrow += dh * 16;
#pragma unroll
        for (int j = 0; j < 4; j++) {
            float4 f = ((const float4*)wrow)[j];
            w2[4*j+0] = pack2(f.x, f.x); w2[4*j+1] = pack2(f.y, f.y);
            w2[4*j+2] = pack2(f.z, f.z); w2[4*j+3] = pack2(f.w, f.w);
        }
        if (dh == 0) {
            float bias = (ch < 128) ? bk[ch] : bv[ch - 128];
            bias2 = pack2(bias, bias);
        }
    }
    __syncthreads();

    // ---- Phase A: all 76 tokens per thread, 16-d half, shfl-combined ----
    {
        const float* ebase = sm + SM_EMB + dh * 16 * ESTR;
#pragma unroll 1
        for (int q = 0; q < 19; q++) {
            const int t0 = q * 4;
            ull a0 = bias2, a1 = bias2, b0 = 0ull, b1 = 0ull;
#pragma unroll
            for (int d = 0; d < 8; d++) {
                ulonglong2 e = *(const ulonglong2*)&ebase[d * ESTR + t0];
                a0 = fma2(e.x, w2[d], a0);
                a1 = fma2(e.y, w2[d], a1);
            }
#pragma unroll
            for (int d = 8; d < 16; d++) {
                ulonglong2 e = *(const ulonglong2*)&ebase[d * ESTR + t0];
                b0 = fma2(e.x, w2[d], b0);
                b1 = fma2(e.y, w2[d], b1);
            }
            ull acc0 = add2(a0, b0), acc1 = add2(a1, b1);
            // combine d-halves across lane pair
            ull p0 = __shfl_xor_sync(0xffffffffu, acc0, 1);
            ull p1 = __shfl_xor_sync(0xffffffffu, acc1, 1);
            ull r  = dh ? add2(acc1, p1) : add2(acc0, p0);
            const int tok = t0 + 2 * dh;     // even lane: t0,t0+1; odd: t0+2,t0+3
            if (ch < 128) {                  // warp-uniform
                sm[SM_K + tok * KSTR + ch]       = lo2(r);
                sm[SM_K + (tok + 1) * KSTR + ch] = hi2(r);
            } else {
                sm[SM_V + tok * VSTR + (ch - 128)]       = lo2(r);
                sm[SM_V + (tok + 1) * VSTR + (ch - 128)] = hi2(r);
            }
        }
    }
    __syncthreads();

    // ---- Phase B: per-(tok,g) sums; hid straight from global ----
    if (tid < 296) {
        float grr = 0.f, gate = 0.f;
        if (bgt >= 0) {
            // issue all hid loads upfront (independent LDG.128, L2-warm)
            float4 h4[8];
#pragma unroll
            for (int j = 0; j < 8; j++) h4[j] = ((const float4*)hrow)[j];

            const float* kp = sm + SM_K + btok * KSTR + bg * 32;
            const float* np = sm + SM_NN + bg * 32;
            const float* vp = sm + SM_V + btok * VSTR;
            ull skk2 = 0ull, shh2 = 0ull, skh2 = 0ull, svv2 = 0ull;
#pragma unroll
            for (int j = 0; j < 8; j++) {
                const int c = j * 4;
                ulonglong2 k2 = *(const ulonglong2*)(kp + c);
                ulonglong2 n2 = *(const ulonglong2*)(np + c);
                ulonglong2 v2 = *(const ulonglong2*)(vp + c);
                ull hx = pack2(h4[j].x, h4[j].y);
                ull hy = pack2(h4[j].z, h4[j].w);
                skk2 = fma2(k2.x, k2.x, skk2);
                shh2 = fma2(hx, hx, shh2);
                skh2 = fma2(mul2(k2.x, hx), n2.x, skh2);
                svv2 = fma2(v2.x, v2.x, svv2);
                skk2 = fma2(k2.y, k2.y, skk2);
                shh2 = fma2(hy, hy, shh2);
                skh2 = fma2(mul2(k2.y, hy), n2.y, skh2);
                svv2 = fma2(v2.y, v2.y, svv2);
            }
            const float skk = lo2(skk2) + hi2(skk2);
            const float shh = lo2(shh2) + hi2(shh2);
            const float skh = lo2(skh2) + hi2(skh2);
            const float svv = lo2(svv2) + hi2(svv2);
            const float rs1 = rsqrtf(skk * (1.f/32.f) + EPSF);
            const float rs2 = rsqrtf(shh * (1.f/32.f) + EPSF);
            const float dot = skh * rs1 * rs2 * 0.17677669529663687f;
            const float sq  = sqrtf(fmaxf(fabsf(dot), 1e-6f));
            const float gs  = (dot > 0.f) ? sq : ((dot < 0.f) ? -sq : 0.f);
            gate = 1.f / (1.f + __expf(-gs));
            grr  = gate * rsqrtf(gate * gate * svv * (1.f/32.f) + EPSF);
        }
        sm[SM_G + btok * 8 + bg * 2 + 0] = grr;
        sm[SM_G + btok * 8 + bg * 2 + 1] = gate;
    }
    __syncthreads();

    // ---- Phase C: conv + SiLU + residual. Warp per token, lane covers 4 ch ----
    {
        const int wid  = tid >> 5, lane = tid & 31;
        const int g    = lane >> 3;
        const int c0   = (lane & 7) * 4;
        const int chb  = g * 32 + c0;
        float4 cw0 = ((const float4*)cvw)[chb + 0];
        float4 cw1 = ((const float4*)cvw)[chb + 1];
        float4 cw2 = ((const float4*)cvw)[chb + 2];
        float4 cw3 = ((const float4*)cvw)[chb + 3];
        ull t9a = pack2(cw0.x, cw1.x), t9b = pack2(cw2.x, cw3.x);
        ull t6a = pack2(cw0.y, cw1.y), t6b = pack2(cw2.y, cw3.y);
        ull t3a = pack2(cw0.z, cw1.z), t3b = pack2(cw2.z, cw3.z);
        ull t0a = pack2(cw0.w, cw1.w), t0b = pack2(cw2.w, cw3.w);
        ull cna = pack2(cnw[chb], cnw[chb+1]), cnb = pack2(cnw[chb+2], cnw[chb+3]);

        for (int mt = wid; mt < TILE; mt += 10) {
            const int tok = mt + HALO;
            const float* gp = sm + SM_G;
            const float grr9 = gp[(tok-9)*8 + g*2], grr6 = gp[(tok-6)*8 + g*2];
            const float grr3 = gp[(tok-3)*8 + g*2], grr0 = gp[(tok  )*8 + g*2];
            const float gate = gp[tok*8 + g*2 + 1];
            const ulonglong2 v9 = *(const ulonglong2*)&sm[SM_V + (tok-9)*VSTR + c0];
            const ulonglong2 v6 = *(const ulonglong2*)&sm[SM_V + (tok-6)*VSTR + c0];
            const ulonglong2 v3 = *(const ulonglong2*)&sm[SM_V + (tok-3)*VSTR + c0];
            const ulonglong2 v0 = *(const ulonglong2*)&sm[SM_V + (tok  )*VSTR + c0];
            const ull g92 = pack2(grr9, grr9), g62 = pack2(grr6, grr6);
            const ull g32 = pack2(grr3, grr3), g02 = pack2(grr0, grr0);
            ull ya = mul2(mul2(t9a, v9.x), g92);
            ull yb = mul2(mul2(t9b, v9.y), g92);
            ya = fma2(mul2(t6a, v6.x), g62, ya);
            yb = fma2(mul2(t6b, v6.y), g62, yb);
            ya = fma2(mul2(t3a, v3.x), g32, ya);
            yb = fma2(mul2(t3b, v3.y), g32, yb);
            ya = fma2(mul2(t0a, v0.x), g02, ya);
            yb = fma2(mul2(t0b, v0.y), g02, yb);
            ya = mul2(ya, cna);
            yb = mul2(yb, cnb);
            const float y0 = lo2(ya), y1 = hi2(ya), y2 = lo2(yb), y3 = hi2(yb);
            const float s0 = y0 / (1.f + __expf(-y0));
            const float s1 = y1 / (1.f + __expf(-y1));
            const float s2 = y2 / (1.f + __expf(-y2));
            const float s3 = y3 / (1.f + __expf(-y3));
            float4 o;
            o.x = fmaf(gate, lo2(v0.x), s0);
            o.y = fmaf(gate, hi2(v0.x), s1);
            o.z = fmaf(gate, lo2(v0.y), s2);
            o.w = fmaf(gate, hi2(v0.y), s3);
            ((float4*)out)[(((base_tok + mt) * 4 + g) * 32 + c0) >> 2] = o;
        }
    }
}

extern "C" void kernel_launch(void* const* d_in, const int* in_sizes, int n_in,
                              void* d_out, int out_size)
{
    const float* emb = (const float*)d_in[0];
    const float* hid = (const float*)d_in[1];
    const float* Wv  = (const float*)d_in[2];
    const float* bv  = (const float*)d_in[3];
    const float* Wk  = (const float*)d_in[4];
    const float* bk  = (const float*)d_in[5];
    const float* n1w = (const float*)d_in[6];
    const float* n2w = (const float*)d_in[7];
    const float* cnw = (const float*)d_in[8];
    const float* cvw = (const float*)d_in[9];
    float* out = (float*)d_out;

    const int T = 8192;
    const int B = in_sizes[0] / (T * 32);
    const size_t smem = SM_FLOATS * sizeof(float);   // 63680 B

    cudaFuncSetAttribute(engram_kernel,
                         cudaFuncAttributeMaxDynamicSharedMemorySize, (int)smem);

    dim3 grid(T / TILE, B);
    engram_kernel<<<grid, 320, smem>>>(emb, hid, Wv, bv, Wk, bk,
                                       n1w, n2w, cnw, cvw, out, T);
}

// round 6
// speedup vs baseline: 1.2802x; 1.2802x over previous
#include <cuda_runtime.h>

#define EPSF 1.1920929e-07f
typedef unsigned long long ull;

constexpr int TILE  = 64;
constexpr int HALO  = 10;
constexpr int NTOK  = 76;          // TILE + HALO + 2
constexpr int NGATE = 74;          // TILE + HALO
constexpr int KSTR  = 132;         // 16B-aligned rows
constexpr int VSTR  = 36;

// shared layout (float offsets)
constexpr int SM_EMB = 0;                     // [76][32] row-major
constexpr int SM_K   = SM_EMB + NTOK * 32;    // [76][132] keys
constexpr int SM_V   = SM_K + NTOK * KSTR;    // [76][36]  values
constexpr int SM_G   = SM_V + NTOK * VSTR;    // [74][4][2] (grr, gate)
constexpr int SM_NN  = SM_G + NGATE * 8;      // [128] n1*n2
constexpr int SM_FLOATS = SM_NN + 128;        // 15920 floats = 63680 B

__device__ __forceinline__ ull fma2(ull a, ull b, ull c) {
    ull d; asm("fma.rn.f32x2 %0, %1, %2, %3;" : "=l"(d) : "l"(a), "l"(b), "l"(c)); return d;
}
__device__ __forceinline__ ull mul2(ull a, ull b) {
    ull d; asm("mul.rn.f32x2 %0, %1, %2;" : "=l"(d) : "l"(a), "l"(b)); return d;
}
__device__ __forceinline__ ull add2(ull a, ull b) {
    ull d; asm("add.rn.f32x2 %0, %1, %2;" : "=l"(d) : "l"(a), "l"(b)); return d;
}
__device__ __forceinline__ ull pack2(float x, float y) {
    ull r; asm("mov.b64 %0, {%1, %2};" : "=l"(r) : "f"(x), "f"(y)); return r;
}
__device__ __forceinline__ float lo2(ull a) { float2 f = *(float2*)&a; return f.x; }
__device__ __forceinline__ float hi2(ull a) { float2 f = *(float2*)&a; return f.y; }

__global__ void __launch_bounds__(320, 3)
engram_kernel(const float* __restrict__ emb, const float* __restrict__ hid,
              const float* __restrict__ Wv,  const float* __restrict__ bv,
              const float* __restrict__ Wk,  const float* __restrict__ bk,
              const float* __restrict__ n1w, const float* __restrict__ n2w,
              const float* __restrict__ cnw, const float* __restrict__ cvw,
              float* __restrict__ out, int T)
{
    extern __shared__ float sm[];
    const int tid        = threadIdx.x;
    const int b          = blockIdx.y;
    const int tile_start = blockIdx.x * TILE;
    const long base_tok  = (long)b * T + tile_start;

    // Phase-B identity (computed early for L2 prefetch of hid)
    const int bg   = (tid < 296) ? tid / 74 : 0;
    const int btok = (tid < 296) ? tid - bg * 74 : 0;
    const int bgt  = tile_start - HALO + btok;
    const float* hrow = hid + (((base_tok - HALO + btok) << 2) + bg) * 32;
    if (tid < 296 && bgt >= 0)
        asm volatile("prefetch.global.L2 [%0];" :: "l"(hrow));

    // ---- stage emb row-major + nn ----
    for (int i4 = tid; i4 < NTOK * 8; i4 += 320) {      // float4 granules
        int tok = i4 >> 3, q = i4 & 7;
        int gt  = tile_start - HALO + tok;
        float4 val = make_float4(0.f, 0.f, 0.f, 0.f);
        if (tok < NGATE && gt >= 0)
            val = ((const float4*)emb)[(base_tok - HALO + tok) * 8 + q];
        ((float4*)(sm + SM_EMB))[i4] = val;
    }
    if (tid < 128) sm[SM_NN + tid] = n1w[tid] * n2w[tid];

    // ---- per-thread projection weights, packed over d (no duplication) ----
    const int ch = tid % 160;       // lanes = consecutive channels
    const int th = tid / 160;       // token half: 0 -> tok 0..37, 1 -> 38..75
    ull w2[16];
    float bias;
    {
        const float* wrow = (ch < 128) ? (Wk + ch * 32) : (Wv + (ch - 128) * 32);
        bias = (ch < 128) ? bk[ch] : bv[ch - 128];
#pragma unroll
        for (int j = 0; j < 8; j++) {
            float4 f = ((const float4*)wrow)[j];
            w2[2*j+0] = pack2(f.x, f.y);
            w2[2*j+1] = pack2(f.z, f.w);
        }
    }
    __syncthreads();

    // ---- Phase A: token loop; 4 indep d-paired FMA2 chains per token ----
    {
        const int t0 = th * 38;
        float* kdst = sm + SM_K + ch;
        float* vdst = sm + SM_V + (ch - 128);
#pragma unroll 2
        for (int i = 0; i < 38; i++) {
            const int tok = t0 + i;
            const ulonglong2* erow = (const ulonglong2*)(sm + SM_EMB + tok * 32);
            ulonglong2 e0 = erow[0], e1 = erow[1], e2 = erow[2], e3 = erow[3];
            ull a = mul2(e0.x, w2[0]);
            ull c = mul2(e0.y, w2[1]);
            ull d = mul2(e1.x, w2[2]);
            ull f = mul2(e1.y, w2[3]);
            a = fma2(e2.x, w2[4], a);
            c = fma2(e2.y, w2[5], c);
            d = fma2(e3.x, w2[6], d);
            f = fma2(e3.y, w2[7], f);
            ulonglong2 e4 = erow[4], e5 = erow[5], e6 = erow[6], e7 = erow[7];
            a = fma2(e4.x, w2[8],  a);
            c = fma2(e4.y, w2[9],  c);
            d = fma2(e5.x, w2[10], d);
            f = fma2(e5.y, w2[11], f);
            a = fma2(e6.x, w2[12], a);
            c = fma2(e6.y, w2[13], c);
            d = fma2(e7.x, w2[14], d);
            f = fma2(e7.y, w2[15], f);
            ull s = add2(add2(a, c), add2(d, f));
            const float r = (lo2(s) + hi2(s)) + bias;
            if (ch < 128) kdst[tok * KSTR] = r;       // warp-uniform branch
            else          vdst[tok * VSTR] = r;
        }
    }
    __syncthreads();

    // ---- Phase B: per-(tok,g) sums; hid straight from global (L2-warm) ----
    if (tid < 296) {
        float grr = 0.f, gate = 0.f;
        if (bgt >= 0) {
            float4 h4[8];
#pragma unroll
            for (int j = 0; j < 8; j++) h4[j] = ((const float4*)hrow)[j];

            const float* kp = sm + SM_K + btok * KSTR + bg * 32;
            const float* np = sm + SM_NN + bg * 32;
            const float* vp = sm + SM_V + btok * VSTR;
            ull skk2 = 0ull, shh2 = 0ull, skh2 = 0ull, svv2 = 0ull;
#pragma unroll
            for (int j = 0; j < 8; j++) {
                const int c = j * 4;
                ulonglong2 k2 = *(const ulonglong2*)(kp + c);
                ulonglong2 n2 = *(const ulonglong2*)(np + c);
                ulonglong2 v2 = *(const ulonglong2*)(vp + c);
                ull hx = pack2(h4[j].x, h4[j].y);
                ull hy = pack2(h4[j].z, h4[j].w);
                skk2 = fma2(k2.x, k2.x, skk2);
                shh2 = fma2(hx, hx, shh2);
                skh2 = fma2(mul2(k2.x, hx), n2.x, skh2);
                svv2 = fma2(v2.x, v2.x, svv2);
                skk2 = fma2(k2.y, k2.y, skk2);
                shh2 = fma2(hy, hy, shh2);
                skh2 = fma2(mul2(k2.y, hy), n2.y, skh2);
                svv2 = fma2(v2.y, v2.y, svv2);
            }
            const float skk = lo2(skk2) + hi2(skk2);
            const float shh = lo2(shh2) + hi2(shh2);
            const float skh = lo2(skh2) + hi2(skh2);
            const float svv = lo2(svv2) + hi2(svv2);
            const float rs1 = rsqrtf(skk * (1.f/32.f) + EPSF);
            const float rs2 = rsqrtf(shh * (1.f/32.f) + EPSF);
            const float dot = skh * rs1 * rs2 * 0.17677669529663687f;
            const float sq  = sqrtf(fmaxf(fabsf(dot), 1e-6f));
            const float gs  = (dot > 0.f) ? sq : ((dot < 0.f) ? -sq : 0.f);
            gate = 1.f / (1.f + __expf(-gs));
            grr  = gate * rsqrtf(gate * gate * svv * (1.f/32.f) + EPSF);
        }
        sm[SM_G + btok * 8 + bg * 2 + 0] = grr;
        sm[SM_G + btok * 8 + bg * 2 + 1] = gate;
    }
    __syncthreads();

    // ---- Phase C: conv + SiLU + residual. Warp per token, lane covers 4 ch ----
    {
        const int wid  = tid >> 5, lane = tid & 31;
        const int g    = lane >> 3;
        const int c0   = (lane & 7) * 4;
        const int chb  = g * 32 + c0;
        float4 cw0 = ((const float4*)cvw)[chb + 0];
        float4 cw1 = ((const float4*)cvw)[chb + 1];
        float4 cw2 = ((const float4*)cvw)[chb + 2];
        float4 cw3 = ((const float4*)cvw)[chb + 3];
        ull t9a = pack2(cw0.x, cw1.x), t9b = pack2(cw2.x, cw3.x);
        ull t6a = pack2(cw0.y, cw1.y), t6b = pack2(cw2.y, cw3.y);
        ull t3a = pack2(cw0.z, cw1.z), t3b = pack2(cw2.z, cw3.z);
        ull t0a = pack2(cw0.w, cw1.w), t0b = pack2(cw2.w, cw3.w);
        ull cna = pack2(cnw[chb], cnw[chb+1]), cnb = pack2(cnw[chb+2], cnw[chb+3]);

        for (int mt = wid; mt < TILE; mt += 10) {
            const int tok = mt + HALO;
            const float* gp = sm + SM_G;
            const float grr9 = gp[(tok-9)*8 + g*2], grr6 = gp[(tok-6)*8 + g*2];
            const float grr3 = gp[(tok-3)*8 + g*2], grr0 = gp[(tok  )*8 + g*2];
            const float gate = gp[tok*8 + g*2 + 1];
            const ulonglong2 v9 = *(const ulonglong2*)&sm[SM_V + (tok-9)*VSTR + c0];
            const ulonglong2 v6 = *(const ulonglong2*)&sm[SM_V + (tok-6)*VSTR + c0];
            const ulonglong2 v3 = *(const ulonglong2*)&sm[SM_V + (tok-3)*VSTR + c0];
            const ulonglong2 v0 = *(const ulonglong2*)&sm[SM_V + (tok  )*VSTR + c0];
            const ull g92 = pack2(grr9, grr9), g62 = pack2(grr6, grr6);
            const ull g32 = pack2(grr3, grr3), g02 = pack2(grr0, grr0);
            ull ya = mul2(mul2(t9a, v9.x), g92);
            ull yb = mul2(mul2(t9b, v9.y), g92);
            ya = fma2(mul2(t6a, v6.x), g62, ya);
            yb = fma2(mul2(t6b, v6.y), g62, yb);
            ya = fma2(mul2(t3a, v3.x), g32, ya);
            yb = fma2(mul2(t3b, v3.y), g32, yb);
            ya = fma2(mul2(t0a, v0.x), g02, ya);
            yb = fma2(mul2(t0b, v0.y), g02, yb);
            ya = mul2(ya, cna);
            yb = mul2(yb, cnb);
            const float y0 = lo2(ya), y1 = hi2(ya), y2 = lo2(yb), y3 = hi2(yb);
            const float s0 = y0 / (1.f + __expf(-y0));
            const float s1 = y1 / (1.f + __expf(-y1));
            const float s2 = y2 / (1.f + __expf(-y2));
            const float s3 = y3 / (1.f + __expf(-y3));
            float4 o;
            o.x = fmaf(gate, lo2(v0.x), s0);
            o.y = fmaf(gate, hi2(v0.x), s1);
            o.z = fmaf(gate, lo2(v0.y), s2);
            o.w = fmaf(gate, hi2(v0.y), s3);
            ((float4*)out)[(((base_tok + mt) * 4 + g) * 32 + c0) >> 2] = o;
        }
    }
}

extern "C" void kernel_launch(void* const* d_in, const int* in_sizes, int n_in,
                              void* d_out, int out_size)
{
    const float* emb = (const float*)d_in[0];
    const float* hid = (const float*)d_in[1];
    const float* Wv  = (const float*)d_in[2];
    const float* bv  = (const float*)d_in[3];
    const float* Wk  = (const float*)d_in[4];
    const float* bk  = (const float*)d_in[5];
    const float* n1w = (const float*)d_in[6];
    const float* n2w = (const float*)d_in[7];
    const float* cnw = (const float*)d_in[8];
    const float* cvw = (const float*)d_in[9];
    float* out = (float*)d_out;

    const int T = 8192;
    const int B = in_sizes[0] / (T * 32);
    const size_t smem = SM_FLOATS * sizeof(float);   // 63680 B

    cudaFuncSetAttribute(engram_kernel,
                         cudaFuncAttributeMaxDynamicSharedMemorySize, (int)smem);

    dim3 grid(T / TILE, B);
    engram_kernel<<<grid, 320, smem>>>(emb, hid, Wv, bv, Wk, bk,
                                       n1w, n2w, cnw, cvw, out, T);
}

// round 7
// speedup vs baseline: 1.5902x; 1.2422x over previous
#include <cuda_runtime.h>

#define EPSF 1.1920929e-07f
typedef unsigned long long ull;

constexpr int TILE  = 64;
constexpr int HALO  = 10;
constexpr int NROWS = 80;          // token rows in smem (5 x m16 tiles)
constexpr int NGATE = 74;          // TILE + HALO
constexpr int ESTR  = 36;          // emb row stride (bank 4r+c permutation)
constexpr int KSTR  = 132;
constexpr int VSTR  = 36;

// shared layout (float offsets)
constexpr int SM_EMB = 0;                      // [80][36]
constexpr int SM_K   = SM_EMB + NROWS * ESTR;  // [80][132] keys (also weight staging)
constexpr int SM_V   = SM_K + NROWS * KSTR;    // [80][36]  values
constexpr int SM_G   = SM_V + NROWS * VSTR;    // [74][4][2] (grr, gate)
constexpr int SM_NN  = SM_G + NGATE * 8;       // [128] n1*n2
constexpr int SM_FLOATS = SM_NN + 128;         // 17040 floats = 68160 B

__device__ __forceinline__ ull fma2(ull a, ull b, ull c) {
    ull d; asm("fma.rn.f32x2 %0, %1, %2, %3;" : "=l"(d) : "l"(a), "l"(b), "l"(c)); return d;
}
__device__ __forceinline__ ull mul2(ull a, ull b) {
    ull d; asm("mul.rn.f32x2 %0, %1, %2;" : "=l"(d) : "l"(a), "l"(b)); return d;
}
__device__ __forceinline__ ull pack2(float x, float y) {
    ull r; asm("mov.b64 %0, {%1, %2};" : "=l"(r) : "f"(x), "f"(y)); return r;
}
__device__ __forceinline__ float lo2(ull a) { float2 f = *(float2*)&a; return f.x; }
__device__ __forceinline__ float hi2(ull a) { float2 f = *(float2*)&a; return f.y; }
__device__ __forceinline__ unsigned f2tf32(float x) {
    unsigned r; asm("cvt.rna.tf32.f32 %0, %1;" : "=r"(r) : "f"(x)); return r;
}
__device__ __forceinline__ void mma8(float* d, unsigned a0, unsigned a1,
                                     unsigned a2, unsigned a3,
                                     unsigned b0, unsigned b1) {
    asm volatile("mma.sync.aligned.m16n8k8.row.col.f32.tf32.tf32.f32 "
                 "{%0,%1,%2,%3}, {%4,%5,%6,%7}, {%8,%9}, {%0,%1,%2,%3};"
                 : "+f"(d[0]), "+f"(d[1]), "+f"(d[2]), "+f"(d[3])
                 : "r"(a0), "r"(a1), "r"(a2), "r"(a3), "r"(b0), "r"(b1));
}

__global__ void __launch_bounds__(320, 3)
engram_kernel(const float* __restrict__ emb, const float* __restrict__ hid,
              const float* __restrict__ Wv,  const float* __restrict__ bv,
              const float* __restrict__ Wk,  const float* __restrict__ bk,
              const float* __restrict__ n1w, const float* __restrict__ n2w,
              const float* __restrict__ cnw, const float* __restrict__ cvw,
              float* __restrict__ out, int T)
{
    extern __shared__ float sm[];
    const int tid        = threadIdx.x;
    const int b          = blockIdx.y;
    const int tile_start = blockIdx.x * TILE;
    const long base_tok  = (long)b * T + tile_start;

    // Phase-B identity (computed early for L2 prefetch of hid)
    const int bg   = (tid < 296) ? tid / 74 : 0;
    const int btok = (tid < 296) ? tid - bg * 74 : 0;
    const int bgt  = tile_start - HALO + btok;
    const float* hrow = hid + (((base_tok - HALO + btok) << 2) + bg) * 32;
    if (tid < 296 && bgt >= 0)
        asm volatile("prefetch.global.L2 [%0];" :: "l"(hrow));

    // ---- stage emb [80][36] (zero-padded), weights coalesced into SM_K, nn ----
    for (int i4 = tid; i4 < NROWS * 8; i4 += 320) {
        int tok = i4 >> 3, q = i4 & 7;
        int gt  = tile_start - HALO + tok;
        float4 val = make_float4(0.f, 0.f, 0.f, 0.f);
        if (tok < NGATE && gt >= 0)
            val = ((const float4*)emb)[(base_tok - HALO + tok) * 8 + q];
        *(float4*)(sm + SM_EMB + tok * ESTR + q * 4) = val;
    }
    for (int i4 = tid; i4 < 160 * 8; i4 += 320) {
        int row = i4 >> 3, q = i4 & 7;
        const float* src = (row < 128 ? Wk + row * 32 : Wv + (row - 128) * 32) + q * 4;
        *(float4*)(sm + SM_K + row * 36 + q * 4) = *(const float4*)src;
    }
    if (tid < 128) sm[SM_NN + tid] = n1w[tid] * n2w[tid];
    __syncthreads();

    const int w  = tid >> 5, l = tid & 31;
    const int lr = l >> 2, lc = l & 3;

    // ---- B fragments (tf32 hi/lo) + bias from staged weights ----
    unsigned bhi[2][4][2], blo[2][4][2];
    float bias0[2], bias1[2];
#pragma unroll
    for (int j = 0; j < 2; j++) {
        const int n0 = w * 16 + j * 8;
        const float* wr = sm + SM_K + (n0 + lr) * 36;
#pragma unroll
        for (int kb = 0; kb < 4; kb++) {
            float w0 = wr[kb * 8 + lc];
            float w1 = wr[kb * 8 + lc + 4];
            unsigned h0 = f2tf32(w0), h1 = f2tf32(w1);
            bhi[j][kb][0] = h0; blo[j][kb][0] = f2tf32(w0 - __uint_as_float(h0));
            bhi[j][kb][1] = h1; blo[j][kb][1] = f2tf32(w1 - __uint_as_float(h1));
        }
        const float* bb = (n0 < 128) ? (bk + n0) : (bv + n0 - 128);
        bias0[j] = bb[2 * lc];
        bias1[j] = bb[2 * lc + 1];
    }
    __syncthreads();   // all B-frag reads done before SM_K is overwritten

    // ---- Phase A: 3xTF32 mma, warp = 16 channels, all 80 token rows ----
#pragma unroll 1
    for (int m = 0; m < 5; m++) {
        const int t0 = m * 16;
        float d0[4], d1[4];
        d0[0] = bias0[0]; d0[1] = bias1[0]; d0[2] = bias0[0]; d0[3] = bias1[0];
        d1[0] = bias0[1]; d1[1] = bias1[1]; d1[2] = bias0[1]; d1[3] = bias1[1];
#pragma unroll
        for (int kb = 0; kb < 4; kb++) {
            const float* ep = sm + SM_EMB + (t0 + lr) * ESTR + kb * 8 + lc;
            float e0 = ep[0];
            float e1 = ep[8 * ESTR];
            float e2 = ep[4];
            float e3 = ep[8 * ESTR + 4];
            unsigned ah0 = f2tf32(e0), al0 = f2tf32(e0 - __uint_as_float(ah0));
            unsigned ah1 = f2tf32(e1), al1 = f2tf32(e1 - __uint_as_float(ah1));
            unsigned ah2 = f2tf32(e2), al2 = f2tf32(e2 - __uint_as_float(ah2));
            unsigned ah3 = f2tf32(e3), al3 = f2tf32(e3 - __uint_as_float(ah3));
            mma8(d0, ah0, ah1, ah2, ah3, bhi[0][kb][0], bhi[0][kb][1]);
            mma8(d0, ah0, ah1, ah2, ah3, blo[0][kb][0], blo[0][kb][1]);
            mma8(d0, al0, al1, al2, al3, bhi[0][kb][0], bhi[0][kb][1]);
            mma8(d1, ah0, ah1, ah2, ah3, bhi[1][kb][0], bhi[1][kb][1]);
            mma8(d1, ah0, ah1, ah2, ah3, blo[1][kb][0], blo[1][kb][1]);
            mma8(d1, al0, al1, al2, al3, bhi[1][kb][0], bhi[1][kb][1]);
        }
        // store D frags: row = t0+lr (+8), cols n0 + 2lc, 2lc+1
        const int n0a = w * 16;
        if (n0a < 128) {    // warp-uniform: warps 0-7 all key channels
            float* kd = sm + SM_K + n0a + 2 * lc;
            *(float2*)(kd + (t0 + lr) * KSTR)         = make_float2(d0[0], d0[1]);
            *(float2*)(kd + (t0 + lr + 8) * KSTR)     = make_float2(d0[2], d0[3]);
            *(float2*)(kd + 8 + (t0 + lr) * KSTR)     = make_float2(d1[0], d1[1]);
            *(float2*)(kd + 8 + (t0 + lr + 8) * KSTR) = make_float2(d1[2], d1[3]);
        } else {            // warps 8,9: value channels
            float* vd = sm + SM_V + (n0a - 128) + 2 * lc;
            *(float2*)(vd + (t0 + lr) * VSTR)         = make_float2(d0[0], d0[1]);
            *(float2*)(vd + (t0 + lr + 8) * VSTR)     = make_float2(d0[2], d0[3]);
            *(float2*)(vd + 8 + (t0 + lr) * VSTR)     = make_float2(d1[0], d1[1]);
            *(float2*)(vd + 8 + (t0 + lr + 8) * VSTR) = make_float2(d1[2], d1[3]);
        }
    }
    __syncthreads();

    // ---- Phase B: per-(tok,g) sums; hid straight from global (L2-warm) ----
    if (tid < 296) {
        float grr = 0.f, gate = 0.f;
        if (bgt >= 0) {
            float4 h4[8];
#pragma unroll
            for (int j = 0; j < 8; j++) h4[j] = ((const float4*)hrow)[j];

            const float* kp = sm + SM_K + btok * KSTR + bg * 32;
            const float* np = sm + SM_NN + bg * 32;
            const float* vp = sm + SM_V + btok * VSTR;
            ull skk2 = 0ull, shh2 = 0ull, skh2 = 0ull, svv2 = 0ull;
#pragma unroll
            for (int j = 0; j < 8; j++) {
                const int c = j * 4;
                ulonglong2 k2 = *(const ulonglong2*)(kp + c);
                ulonglong2 n2 = *(const ulonglong2*)(np + c);
                ulonglong2 v2 = *(const ulonglong2*)(vp + c);
                ull hx = pack2(h4[j].x, h4[j].y);
                ull hy = pack2(h4[j].z, h4[j].w);
                skk2 = fma2(k2.x, k2.x, skk2);
                shh2 = fma2(hx, hx, shh2);
                skh2 = fma2(mul2(k2.x, hx), n2.x, skh2);
                svv2 = fma2(v2.x, v2.x, svv2);
                skk2 = fma2(k2.y, k2.y, skk2);
                shh2 = fma2(hy, hy, shh2);
                skh2 = fma2(mul2(k2.y, hy), n2.y, skh2);
                svv2 = fma2(v2.y, v2.y, svv2);
            }
            const float skk = lo2(skk2) + hi2(skk2);
            const float shh = lo2(shh2) + hi2(shh2);
            const float skh = lo2(skh2) + hi2(skh2);
            const float svv = lo2(svv2) + hi2(svv2);
            const float rs1 = rsqrtf(skk * (1.f/32.f) + EPSF);
            const float rs2 = rsqrtf(shh * (1.f/32.f) + EPSF);
            const float dot = skh * rs1 * rs2 * 0.17677669529663687f;
            const float sq  = sqrtf(fmaxf(fabsf(dot), 1e-6f));
            const float gs  = (dot > 0.f) ? sq : ((dot < 0.f) ? -sq : 0.f);
            gate = 1.f / (1.f + __expf(-gs));
            grr  = gate * rsqrtf(gate * gate * svv * (1.f/32.f) + EPSF);
        }
        sm[SM_G + btok * 8 + bg * 2 + 0] = grr;
        sm[SM_G + btok * 8 + bg * 2 + 1] = gate;
    }
    __syncthreads();

    // ---- Phase C: conv + SiLU + residual. Warp per token, lane covers 4 ch ----
    {
        const int lane = l;
        const int g    = lane >> 3;
        const int c0   = (lane & 7) * 4;
        const int chb  = g * 32 + c0;
        float4 cw0 = ((const float4*)cvw)[chb + 0];
        float4 cw1 = ((const float4*)cvw)[chb + 1];
        float4 cw2 = ((const float4*)cvw)[chb + 2];
        float4 cw3 = ((const float4*)cvw)[chb + 3];
        ull t9a = pack2(cw0.x, cw1.x), t9b = pack2(cw2.x, cw3.x);
        ull t6a = pack2(cw0.y, cw1.y), t6b = pack2(cw2.y, cw3.y);
        ull t3a = pack2(cw0.z, cw1.z), t3b = pack2(cw2.z, cw3.z);
        ull t0a = pack2(cw0.w, cw1.w), t0b = pack2(cw2.w, cw3.w);
        ull cna = pack2(cnw[chb], cnw[chb+1]), cnb = pack2(cnw[chb+2], cnw[chb+3]);

        for (int mt = w; mt < TILE; mt += 10) {
            const int tok = mt + HALO;
            const float* gp = sm + SM_G;
            const float grr9 = gp[(tok-9)*8 + g*2], grr6 = gp[(tok-6)*8 + g*2];
            const float grr3 = gp[(tok-3)*8 + g*2], grr0 = gp[(tok  )*8 + g*2];
            const float gate = gp[tok*8 + g*2 + 1];
            const ulonglong2 v9 = *(const ulonglong2*)&sm[SM_V + (tok-9)*VSTR + c0];
            const ulonglong2 v6 = *(const ulonglong2*)&sm[SM_V + (tok-6)*VSTR + c0];
            const ulonglong2 v3 = *(const ulonglong2*)&sm[SM_V + (tok-3)*VSTR + c0];
            const ulonglong2 v0 = *(const ulonglong2*)&sm[SM_V + (tok  )*VSTR + c0];
            const ull g92 = pack2(grr9, grr9), g62 = pack2(grr6, grr6);
            const ull g32 = pack2(grr3, grr3), g02 = pack2(grr0, grr0);
            ull ya = mul2(mul2(t9a, v9.x), g92);
            ull yb = mul2(mul2(t9b, v9.y), g92);
            ya = fma2(mul2(t6a, v6.x), g62, ya);
            yb = fma2(mul2(t6b, v6.y), g62, yb);
            ya = fma2(mul2(t3a, v3.x), g32, ya);
            yb = fma2(mul2(t3b, v3.y), g32, yb);
            ya = fma2(mul2(t0a, v0.x), g02, ya);
            yb = fma2(mul2(t0b, v0.y), g02, yb);
            ya = mul2(ya, cna);
            yb = mul2(yb, cnb);
            const float y0 = lo2(ya), y1 = hi2(ya), y2 = lo2(yb), y3 = hi2(yb);
            const float s0 = y0 / (1.f + __expf(-y0));
            const float s1 = y1 / (1.f + __expf(-y1));
            const float s2 = y2 / (1.f + __expf(-y2));
            const float s3 = y3 / (1.f + __expf(-y3));
            float4 o;
            o.x = fmaf(gate, lo2(v0.x), s0);
            o.y = fmaf(gate, hi2(v0.x), s1);
            o.z = fmaf(gate, lo2(v0.y), s2);
            o.w = fmaf(gate, hi2(v0.y), s3);
            ((float4*)out)[(((base_tok + mt) * 4 + g) * 32 + c0) >> 2] = o;
        }
    }
}

extern "C" void kernel_launch(void* const* d_in, const int* in_sizes, int n_in,
                              void* d_out, int out_size)
{
    const float* emb = (const float*)d_in[0];
    const float* hid = (const float*)d_in[1];
    const float* Wv  = (const float*)d_in[2];
    const float* bv  = (const float*)d_in[3];
    const float* Wk  = (const float*)d_in[4];
    const float* bk  = (const float*)d_in[5];
    const float* n1w = (const float*)d_in[6];
    const float* n2w = (const float*)d_in[7];
    const float* cnw = (const float*)d_in[8];
    const float* cvw = (const float*)d_in[9];
    float* out = (float*)d_out;

    const int T = 8192;
    const int B = in_sizes[0] / (T * 32);
    const size_t smem = SM_FLOATS * sizeof(float);   // 68160 B

    cudaFuncSetAttribute(engram_kernel,
                         cudaFuncAttributeMaxDynamicSharedMemorySize, (int)smem);

    dim3 grid(T / TILE, B);
    engram_kernel<<<grid, 320, smem>>>(emb, hid, Wv, bv, Wk, bk,
                                       n1w, n2w, cnw, cvw, out, T);
}

// round 8
// speedup vs baseline: 1.8439x; 1.1595x over previous
#include <cuda_runtime.h>

#define EPSF 1.1920929e-07f
typedef unsigned long long ull;

constexpr int TILE  = 64;
constexpr int HALO  = 10;
constexpr int NROWS = 80;          // token rows (5 x m16 tiles)
constexpr int NGATE = 74;          // TILE + HALO
constexpr int PSTR  = 20;          // u32 stride of packed bf16x2 arrays (bank-perm)
constexpr int KSTR  = 132;
constexpr int VSTR  = 36;

// shared layout (32-bit word offsets)
constexpr int SM_EHI = 0;                      // [80][20] u32 bf16x2 (emb hi)
constexpr int SM_ELO = SM_EHI + NROWS * PSTR;  // [80][20] u32 (emb lo)
constexpr int SM_K   = SM_ELO + NROWS * PSTR;  // [80][132] f32 keys (weight staging first)
constexpr int SM_V   = SM_K + NROWS * KSTR;    // [80][36] f32 values
constexpr int SM_G   = SM_V + NROWS * VSTR;    // [74][4][2] (grr, gate)
constexpr int SM_NN  = SM_G + NGATE * 8;       // [128] n1*n2
constexpr int SM_FLOATS = SM_NN + 128;         // 17360 words = 69440 B

__device__ __forceinline__ ull fma2(ull a, ull b, ull c) {
    ull d; asm("fma.rn.f32x2 %0, %1, %2, %3;" : "=l"(d) : "l"(a), "l"(b), "l"(c)); return d;
}
__device__ __forceinline__ ull mul2(ull a, ull b) {
    ull d; asm("mul.rn.f32x2 %0, %1, %2;" : "=l"(d) : "l"(a), "l"(b)); return d;
}
__device__ __forceinline__ ull pack2(float x, float y) {
    ull r; asm("mov.b64 %0, {%1, %2};" : "=l"(r) : "f"(x), "f"(y)); return r;
}
__device__ __forceinline__ float lo2(ull a) { float2 f = *(float2*)&a; return f.x; }
__device__ __forceinline__ float hi2(ull a) { float2 f = *(float2*)&a; return f.y; }

// split (x0,x1) into bf16x2 hi + bf16x2 lo (lo = exact residual rounded to bf16)
__device__ __forceinline__ void split_bf16x2(float x0, float x1,
                                             unsigned& uh, unsigned& ul) {
    unsigned h;
    asm("cvt.rn.bf16x2.f32 %0, %1, %2;" : "=r"(h) : "f"(x1), "f"(x0));
    float h0 = __uint_as_float(h << 16);
    float h1 = __uint_as_float(h & 0xffff0000u);
    float l0 = x0 - h0, l1 = x1 - h1;
    asm("cvt.rn.bf16x2.f32 %0, %1, %2;" : "=r"(ul) : "f"(l1), "f"(l0));
    uh = h;
}

__device__ __forceinline__ void mma16(float* d, unsigned a0, unsigned a1,
                                      unsigned a2, unsigned a3,
                                      unsigned b0, unsigned b1) {
    asm volatile("mma.sync.aligned.m16n8k16.row.col.f32.bf16.bf16.f32 "
                 "{%0,%1,%2,%3}, {%4,%5,%6,%7}, {%8,%9}, {%0,%1,%2,%3};"
                 : "+f"(d[0]), "+f"(d[1]), "+f"(d[2]), "+f"(d[3])
                 : "r"(a0), "r"(a1), "r"(a2), "r"(a3), "r"(b0), "r"(b1));
}

__global__ void __launch_bounds__(320, 3)
engram_kernel(const float* __restrict__ emb, const float* __restrict__ hid,
              const float* __restrict__ Wv,  const float* __restrict__ bv,
              const float* __restrict__ Wk,  const float* __restrict__ bk,
              const float* __restrict__ n1w, const float* __restrict__ n2w,
              const float* __restrict__ cnw, const float* __restrict__ cvw,
              float* __restrict__ out, int T)
{
    extern __shared__ float sm[];
    unsigned* ehi = (unsigned*)(sm + SM_EHI);
    unsigned* elo = (unsigned*)(sm + SM_ELO);
    unsigned* whi = (unsigned*)(sm + SM_K);          // weight staging (transient)
    unsigned* wlo = whi + 160 * PSTR;

    const int tid        = threadIdx.x;
    const int b          = blockIdx.y;
    const int tile_start = blockIdx.x * TILE;
    const long base_tok  = (long)b * T + tile_start;

    // Phase-B identity (early, for L2 prefetch of hid)
    const int bg   = (tid < 296) ? tid / 74 : 0;
    const int btok = (tid < 296) ? tid - bg * 74 : 0;
    const int bgt  = tile_start - HALO + btok;
    const float* hrow = hid + (((base_tok - HALO + btok) << 2) + bg) * 32;
    if (tid < 296 && bgt >= 0)
        asm volatile("prefetch.global.L2 [%0];" :: "l"(hrow));

    // ---- stage emb (hi/lo bf16x2), weights (hi/lo), nn ----
    for (int i4 = tid; i4 < NROWS * 8; i4 += 320) {
        int tok = i4 >> 3, q = i4 & 7;
        int gt  = tile_start - HALO + tok;
        float4 val = make_float4(0.f, 0.f, 0.f, 0.f);
        if (tok < NGATE && gt >= 0)
            val = ((const float4*)emb)[(base_tok - HALO + tok) * 8 + q];
        unsigned h0, l0, h1, l1;
        split_bf16x2(val.x, val.y, h0, l0);
        split_bf16x2(val.z, val.w, h1, l1);
        const int base = tok * PSTR + 2 * q;
        ehi[base] = h0; ehi[base + 1] = h1;
        elo[base] = l0; elo[base + 1] = l1;
    }
    for (int i4 = tid; i4 < 160 * 8; i4 += 320) {
        int row = i4 >> 3, q = i4 & 7;
        const float* src = (row < 128 ? Wk + row * 32 : Wv + (row - 128) * 32) + q * 4;
        float4 val = *(const float4*)src;
        unsigned h0, l0, h1, l1;
        split_bf16x2(val.x, val.y, h0, l0);
        split_bf16x2(val.z, val.w, h1, l1);
        const int base = row * PSTR + 2 * q;
        whi[base] = h0; whi[base + 1] = h1;
        wlo[base] = l0; wlo[base + 1] = l1;
    }
    if (tid < 128) sm[SM_NN + tid] = n1w[tid] * n2w[tid];
    __syncthreads();

    const int w  = tid >> 5, l = tid & 31;
    const int lr = l >> 2, lc = l & 3;

    // ---- B fragments (bf16 hi/lo) + bias ----
    unsigned bh[2][2][2], blf[2][2][2];
    float bias0[2], bias1[2];
#pragma unroll
    for (int j = 0; j < 2; j++) {
        const int n0 = w * 16 + j * 8;
        const unsigned* wh = whi + (n0 + lr) * PSTR;
        const unsigned* wl = wlo + (n0 + lr) * PSTR;
#pragma unroll
        for (int kb = 0; kb < 2; kb++) {
            bh[j][kb][0]  = wh[kb * 8 + lc];
            bh[j][kb][1]  = wh[kb * 8 + lc + 4];
            blf[j][kb][0] = wl[kb * 8 + lc];
            blf[j][kb][1] = wl[kb * 8 + lc + 4];
        }
        const float* bb = (n0 < 128) ? (bk + n0) : (bv + n0 - 128);
        bias0[j] = bb[2 * lc];
        bias1[j] = bb[2 * lc + 1];
    }
    __syncthreads();   // weight staging region about to be overwritten by D

    // ---- Phase A: 3-term bf16 mma, warp = 16 channels, 80 token rows ----
#pragma unroll 1
    for (int m = 0; m < 5; m++) {
        const int t0 = m * 16;
        float d0[4], d1[4];
        d0[0] = bias0[0]; d0[1] = bias1[0]; d0[2] = bias0[0]; d0[3] = bias1[0];
        d1[0] = bias0[1]; d1[1] = bias1[1]; d1[2] = bias0[1]; d1[3] = bias1[1];
#pragma unroll
        for (int kb = 0; kb < 2; kb++) {
            const int base = (t0 + lr) * PSTR + kb * 8 + lc;
            unsigned a0 = ehi[base],     a1 = ehi[base + 8 * PSTR];
            unsigned a2 = ehi[base + 4], a3 = ehi[base + 8 * PSTR + 4];
            unsigned q0 = elo[base],     q1 = elo[base + 8 * PSTR];
            unsigned q2 = elo[base + 4], q3 = elo[base + 8 * PSTR + 4];
            mma16(d0, q0, q1, q2, q3, bh[0][kb][0],  bh[0][kb][1]);   // Al*Bh
            mma16(d0, a0, a1, a2, a3, blf[0][kb][0], blf[0][kb][1]);  // Ah*Bl
            mma16(d0, a0, a1, a2, a3, bh[0][kb][0],  bh[0][kb][1]);   // Ah*Bh
            mma16(d1, q0, q1, q2, q3, bh[1][kb][0],  bh[1][kb][1]);
            mma16(d1, a0, a1, a2, a3, blf[1][kb][0], blf[1][kb][1]);
            mma16(d1, a0, a1, a2, a3, bh[1][kb][0],  bh[1][kb][1]);
        }
        const int n0a = w * 16;
        if (n0a < 128) {    // warp-uniform: warps 0-7 key channels
            float* kd = sm + SM_K + n0a + 2 * lc;
            *(float2*)(kd + (t0 + lr) * KSTR)         = make_float2(d0[0], d0[1]);
            *(float2*)(kd + (t0 + lr + 8) * KSTR)     = make_float2(d0[2], d0[3]);
            *(float2*)(kd + 8 + (t0 + lr) * KSTR)     = make_float2(d1[0], d1[1]);
            *(float2*)(kd + 8 + (t0 + lr + 8) * KSTR) = make_float2(d1[2], d1[3]);
        } else {            // warps 8,9: value channels
            float* vd = sm + SM_V + (n0a - 128) + 2 * lc;
            *(float2*)(vd + (t0 + lr) * VSTR)         = make_float2(d0[0], d0[1]);
            *(float2*)(vd + (t0 + lr + 8) * VSTR)     = make_float2(d0[2], d0[3]);
            *(float2*)(vd + 8 + (t0 + lr) * VSTR)     = make_float2(d1[0], d1[1]);
            *(float2*)(vd + 8 + (t0 + lr + 8) * VSTR) = make_float2(d1[2], d1[3]);
        }
    }
    __syncthreads();

    // ---- Phase B: per-(tok,g) sums; hid straight from global (L2-warm) ----
    if (tid < 296) {
        float grr = 0.f, gate = 0.f;
        if (bgt >= 0) {
            float4 h4[8];
#pragma unroll
            for (int j = 0; j < 8; j++) h4[j] = ((const float4*)hrow)[j];

            const float* kp = sm + SM_K + btok * KSTR + bg * 32;
            const float* np = sm + SM_NN + bg * 32;
            const float* vp = sm + SM_V + btok * VSTR;
            ull skk2 = 0ull, shh2 = 0ull, skh2 = 0ull, svv2 = 0ull;
#pragma unroll
            for (int j = 0; j < 8; j++) {
                const int c = j * 4;
                ulonglong2 k2 = *(const ulonglong2*)(kp + c);
                ulonglong2 n2 = *(const ulonglong2*)(np + c);
                ulonglong2 v2 = *(const ulonglong2*)(vp + c);
                ull hx = pack2(h4[j].x, h4[j].y);
                ull hy = pack2(h4[j].z, h4[j].w);
                skk2 = fma2(k2.x, k2.x, skk2);
                shh2 = fma2(hx, hx, shh2);
                skh2 = fma2(mul2(k2.x, hx), n2.x, skh2);
                svv2 = fma2(v2.x, v2.x, svv2);
                skk2 = fma2(k2.y, k2.y, skk2);
                shh2 = fma2(hy, hy, shh2);
                skh2 = fma2(mul2(k2.y, hy), n2.y, skh2);
                svv2 = fma2(v2.y, v2.y, svv2);
            }
            const float skk = lo2(skk2) + hi2(skk2);
            const float shh = lo2(shh2) + hi2(shh2);
            const float skh = lo2(skh2) + hi2(skh2);
            const float svv = lo2(svv2) + hi2(svv2);
            const float rs1 = rsqrtf(skk * (1.f/32.f) + EPSF);
            const float rs2 = rsqrtf(shh * (1.f/32.f) + EPSF);
            const float dot = skh * rs1 * rs2 * 0.17677669529663687f;
            const float sq  = sqrtf(fmaxf(fabsf(dot), 1e-6f));
            const float gs  = (dot > 0.f) ? sq : ((dot < 0.f) ? -sq : 0.f);
            gate = 1.f / (1.f + __expf(-gs));
            grr  = gate * rsqrtf(gate * gate * svv * (1.f/32.f) + EPSF);
        }
        sm[SM_G + btok * 8 + bg * 2 + 0] = grr;
        sm[SM_G + btok * 8 + bg * 2 + 1] = gate;
    }
    __syncthreads();

    // ---- Phase C: conv + SiLU + residual. Warp per token, lane covers 4 ch ----
    {
        const int g    = l >> 3;
        const int c0   = (l & 7) * 4;
        const int chb  = g * 32 + c0;
        float4 cw0 = ((const float4*)cvw)[chb + 0];
        float4 cw1 = ((const float4*)cvw)[chb + 1];
        float4 cw2 = ((const float4*)cvw)[chb + 2];
        float4 cw3 = ((const float4*)cvw)[chb + 3];
        ull t9a = pack2(cw0.x, cw1.x), t9b = pack2(cw2.x, cw3.x);
        ull t6a = pack2(cw0.y, cw1.y), t6b = pack2(cw2.y, cw3.y);
        ull t3a = pack2(cw0.z, cw1.z), t3b = pack2(cw2.z, cw3.z);
        ull t0a = pack2(cw0.w, cw1.w), t0b = pack2(cw2.w, cw3.w);
        ull cna = pack2(cnw[chb], cnw[chb+1]), cnb = pack2(cnw[chb+2], cnw[chb+3]);

        for (int mt = w; mt < TILE; mt += 10) {
            const int tok = mt + HALO;
            const float* gp = sm + SM_G;
            const float grr9 = gp[(tok-9)*8 + g*2], grr6 = gp[(tok-6)*8 + g*2];
            const float grr3 = gp[(tok-3)*8 + g*2], grr0 = gp[(tok  )*8 + g*2];
            const float gate = gp[tok*8 + g*2 + 1];
            const ulonglong2 v9 = *(const ulonglong2*)&sm[SM_V + (tok-9)*VSTR + c0];
            const ulonglong2 v6 = *(const ulonglong2*)&sm[SM_V + (tok-6)*VSTR + c0];
            const ulonglong2 v3 = *(const ulonglong2*)&sm[SM_V + (tok-3)*VSTR + c0];
            const ulonglong2 v0 = *(const ulonglong2*)&sm[SM_V + (tok  )*VSTR + c0];
            const ull g92 = pack2(grr9, grr9), g62 = pack2(grr6, grr6);
            const ull g32 = pack2(grr3, grr3), g02 = pack2(grr0, grr0);
            ull ya = mul2(mul2(t9a, v9.x), g92);
            ull yb = mul2(mul2(t9b, v9.y), g92);
            ya = fma2(mul2(t6a, v6.x), g62, ya);
            yb = fma2(mul2(t6b, v6.y), g62, yb);
            ya = fma2(mul2(t3a, v3.x), g32, ya);
            yb = fma2(mul2(t3b, v3.y), g32, yb);
            ya = fma2(mul2(t0a, v0.x), g02, ya);
            yb = fma2(mul2(t0b, v0.y), g02, yb);
            ya = mul2(ya, cna);
            yb = mul2(yb, cnb);
            const float y0 = lo2(ya), y1 = hi2(ya), y2 = lo2(yb), y3 = hi2(yb);
            const float s0 = y0 / (1.f + __expf(-y0));
            const float s1 = y1 / (1.f + __expf(-y1));
            const float s2 = y2 / (1.f + __expf(-y2));
            const float s3 = y3 / (1.f + __expf(-y3));
            float4 o;
            o.x = fmaf(gate, lo2(v0.x), s0);
            o.y = fmaf(gate, hi2(v0.x), s1);
            o.z = fmaf(gate, lo2(v0.y), s2);
            o.w = fmaf(gate, hi2(v0.y), s3);
            ((float4*)out)[(((base_tok + mt) * 4 + g) * 32 + c0) >> 2] = o;
        }
    }
}

extern "C" void kernel_launch(void* const* d_in, const int* in_sizes, int n_in,
                              void* d_out, int out_size)
{
    const float* emb = (const float*)d_in[0];
    const float* hid = (const float*)d_in[1];
    const float* Wv  = (const float*)d_in[2];
    const float* bv  = (const float*)d_in[3];
    const float* Wk  = (const float*)d_in[4];
    const float* bk  = (const float*)d_in[5];
    const float* n1w = (const float*)d_in[6];
    const float* n2w = (const float*)d_in[7];
    const float* cnw = (const float*)d_in[8];
    const float* cvw = (const float*)d_in[9];
    float* out = (float*)d_out;

    const int T = 8192;
    const int B = in_sizes[0] / (T * 32);
    const size_t smem = SM_FLOATS * sizeof(float);   // 69440 B

    cudaFuncSetAttribute(engram_kernel,
                         cudaFuncAttributeMaxDynamicSharedMemorySize, (int)smem);

    dim3 grid(T / TILE, B);
    engram_kernel<<<grid, 320, smem>>>(emb, hid, Wv, bv, Wk, bk,
                                       n1w, n2w, cnw, cvw, out, T);
}

// round 9
// speedup vs baseline: 1.8839x; 1.0217x over previous
#include <cuda_runtime.h>

#define EPSF 1.1920929e-07f
typedef unsigned long long ull;

constexpr int TILE  = 64;
constexpr int HALO  = 10;
constexpr int NROWS = 80;          // token rows (5 x m16 tiles)
constexpr int NGATE = 74;          // TILE + HALO
constexpr int NITEM = NGATE * 4;   // 296 (tok,g) items
constexpr int PSTR  = 20;          // u32 stride of packed bf16x2 arrays (bank-perm)
constexpr int KSTR  = 132;
constexpr int VSTR  = 36;

// shared layout (32-bit word offsets)
constexpr int SM_EHI = 0;                      // [80][20] u32 bf16x2 (emb hi)
constexpr int SM_ELO = SM_EHI + NROWS * PSTR;  // [80][20] u32 (emb lo)
constexpr int SM_K   = SM_ELO + NROWS * PSTR;  // [80][132] f32 keys (weight staging first)
constexpr int SM_V   = SM_K + NROWS * KSTR;    // [80][36] f32 values
constexpr int SM_G   = SM_V + NROWS * VSTR;    // [74][4][2] (grr, gate)
constexpr int SM_NN  = SM_G + NGATE * 8;       // [128] n1*n2
constexpr int SM_FLOATS = SM_NN + 128;         // 17360 words = 69440 B

__device__ __forceinline__ ull fma2(ull a, ull b, ull c) {
    ull d; asm("fma.rn.f32x2 %0, %1, %2, %3;" : "=l"(d) : "l"(a), "l"(b), "l"(c)); return d;
}
__device__ __forceinline__ ull mul2(ull a, ull b) {
    ull d; asm("mul.rn.f32x2 %0, %1, %2;" : "=l"(d) : "l"(a), "l"(b)); return d;
}
__device__ __forceinline__ ull add2(ull a, ull b) {
    ull d; asm("add.rn.f32x2 %0, %1, %2;" : "=l"(d) : "l"(a), "l"(b)); return d;
}
__device__ __forceinline__ ull pack2(float x, float y) {
    ull r; asm("mov.b64 %0, {%1, %2};" : "=l"(r) : "f"(x), "f"(y)); return r;
}
__device__ __forceinline__ float lo2(ull a) { float2 f = *(float2*)&a; return f.x; }
__device__ __forceinline__ float hi2(ull a) { float2 f = *(float2*)&a; return f.y; }

// split (x0,x1) into bf16x2 hi + bf16x2 lo (lo = residual rounded to bf16)
__device__ __forceinline__ void split_bf16x2(float x0, float x1,
                                             unsigned& uh, unsigned& ul) {
    unsigned h;
    asm("cvt.rn.bf16x2.f32 %0, %1, %2;" : "=r"(h) : "f"(x1), "f"(x0));
    float h0 = __uint_as_float(h << 16);
    float h1 = __uint_as_float(h & 0xffff0000u);
    float l0 = x0 - h0, l1 = x1 - h1;
    asm("cvt.rn.bf16x2.f32 %0, %1, %2;" : "=r"(ul) : "f"(l1), "f"(l0));
    uh = h;
}

__device__ __forceinline__ void mma16(float* d, unsigned a0, unsigned a1,
                                      unsigned a2, unsigned a3,
                                      unsigned b0, unsigned b1) {
    asm volatile("mma.sync.aligned.m16n8k16.row.col.f32.bf16.bf16.f32 "
                 "{%0,%1,%2,%3}, {%4,%5,%6,%7}, {%8,%9}, {%0,%1,%2,%3};"
                 : "+f"(d[0]), "+f"(d[1]), "+f"(d[2]), "+f"(d[3])
                 : "r"(a0), "r"(a1), "r"(a2), "r"(a3), "r"(b0), "r"(b1));
}

__global__ void __launch_bounds__(320, 3)
engram_kernel(const float* __restrict__ emb, const float* __restrict__ hid,
              const float* __restrict__ Wv,  const float* __restrict__ bv,
              const float* __restrict__ Wk,  const float* __restrict__ bk,
              const float* __restrict__ n1w, const float* __restrict__ n2w,
              const float* __restrict__ cnw, const float* __restrict__ cvw,
              float* __restrict__ out, int T)
{
    extern __shared__ float sm[];
    unsigned* ehi = (unsigned*)(sm + SM_EHI);
    unsigned* elo = (unsigned*)(sm + SM_ELO);
    unsigned* whi = (unsigned*)(sm + SM_K);          // weight staging (transient)
    unsigned* wlo = whi + 160 * PSTR;

    const int tid        = threadIdx.x;
    const int b          = blockIdx.y;
    const int tile_start = blockIdx.x * TILE;
    const long base_tok  = (long)b * T + tile_start;
    const float* hbase   = hid + (base_tok - HALO) * 128;   // row r = (tok*4+g)

    // ---- stage emb (hi/lo bf16x2), weights (hi/lo), nn ----
    for (int i4 = tid; i4 < NROWS * 8; i4 += 320) {
        int tok = i4 >> 3, q = i4 & 7;
        int gt  = tile_start - HALO + tok;
        float4 val = make_float4(0.f, 0.f, 0.f, 0.f);
        if (tok < NGATE && gt >= 0)
            val = ((const float4*)emb)[(base_tok - HALO + tok) * 8 + q];
        unsigned h0, l0, h1, l1;
        split_bf16x2(val.x, val.y, h0, l0);
        split_bf16x2(val.z, val.w, h1, l1);
        const int base = tok * PSTR + 2 * q;
        ehi[base] = h0; ehi[base + 1] = h1;
        elo[base] = l0; elo[base + 1] = l1;
    }
    for (int i4 = tid; i4 < 160 * 8; i4 += 320) {
        int row = i4 >> 3, q = i4 & 7;
        const float* src = (row < 128 ? Wk + row * 32 : Wv + (row - 128) * 32) + q * 4;
        float4 val = *(const float4*)src;
        unsigned h0, l0, h1, l1;
        split_bf16x2(val.x, val.y, h0, l0);
        split_bf16x2(val.z, val.w, h1, l1);
        const int base = row * PSTR + 2 * q;
        whi[base] = h0; whi[base + 1] = h1;
        wlo[base] = l0; wlo[base + 1] = l1;
    }
    if (tid < 128) sm[SM_NN + tid] = n1w[tid] * n2w[tid];
    __syncthreads();

    const int w  = tid >> 5, l = tid & 31;
    const int lr = l >> 2, lc = l & 3;

    // ---- B fragments (bf16 hi/lo) + bias ----
    unsigned bh[2][2][2], blf[2][2][2];
    float bias0[2], bias1[2];
#pragma unroll
    for (int j = 0; j < 2; j++) {
        const int n0 = w * 16 + j * 8;
        const unsigned* wh = whi + (n0 + lr) * PSTR;
        const unsigned* wl = wlo + (n0 + lr) * PSTR;
#pragma unroll
        for (int kb = 0; kb < 2; kb++) {
            bh[j][kb][0]  = wh[kb * 8 + lc];
            bh[j][kb][1]  = wh[kb * 8 + lc + 4];
            blf[j][kb][0] = wl[kb * 8 + lc];
            blf[j][kb][1] = wl[kb * 8 + lc + 4];
        }
        const float* bb = (n0 < 128) ? (bk + n0) : (bv + n0 - 128);
        bias0[j] = bb[2 * lc];
        bias1[j] = bb[2 * lc + 1];
    }
    __syncthreads();   // weight staging region about to be overwritten by D

    // ---- Phase A: 3-term bf16 mma, warp = 16 channels, 80 token rows ----
#pragma unroll 1
    for (int m = 0; m < 5; m++) {
        const int t0 = m * 16;
        float d0[4], d1[4];
        d0[0] = bias0[0]; d0[1] = bias1[0]; d0[2] = bias0[0]; d0[3] = bias1[0];
        d1[0] = bias0[1]; d1[1] = bias1[1]; d1[2] = bias0[1]; d1[3] = bias1[1];
#pragma unroll
        for (int kb = 0; kb < 2; kb++) {
            const int base = (t0 + lr) * PSTR + kb * 8 + lc;
            unsigned a0 = ehi[base],     a1 = ehi[base + 8 * PSTR];
            unsigned a2 = ehi[base + 4], a3 = ehi[base + 8 * PSTR + 4];
            unsigned q0 = elo[base],     q1 = elo[base + 8 * PSTR];
            unsigned q2 = elo[base + 4], q3 = elo[base + 8 * PSTR + 4];
            mma16(d0, q0, q1, q2, q3, bh[0][kb][0],  bh[0][kb][1]);   // Al*Bh
            mma16(d0, a0, a1, a2, a3, blf[0][kb][0], blf[0][kb][1]);  // Ah*Bl
            mma16(d0, a0, a1, a2, a3, bh[0][kb][0],  bh[0][kb][1]);   // Ah*Bh
            mma16(d1, q0, q1, q2, q3, bh[1][kb][0],  bh[1][kb][1]);
            mma16(d1, a0, a1, a2, a3, blf[1][kb][0], blf[1][kb][1]);
            mma16(d1, a0, a1, a2, a3, bh[1][kb][0],  bh[1][kb][1]);
        }
        const int n0a = w * 16;
        if (n0a < 128) {    // warp-uniform: warps 0-7 key channels
            float* kd = sm + SM_K + n0a + 2 * lc;
            *(float2*)(kd + (t0 + lr) * KSTR)         = make_float2(d0[0], d0[1]);
            *(float2*)(kd + (t0 + lr + 8) * KSTR)     = make_float2(d0[2], d0[3]);
            *(float2*)(kd + 8 + (t0 + lr) * KSTR)     = make_float2(d1[0], d1[1]);
            *(float2*)(kd + 8 + (t0 + lr + 8) * KSTR) = make_float2(d1[2], d1[3]);
        } else {            // warps 8,9: value channels
            float* vd = sm + SM_V + (n0a - 128) + 2 * lc;
            *(float2*)(vd + (t0 + lr) * VSTR)         = make_float2(d0[0], d0[1]);
            *(float2*)(vd + (t0 + lr + 8) * VSTR)     = make_float2(d0[2], d0[3]);
            *(float2*)(vd + 8 + (t0 + lr) * VSTR)     = make_float2(d1[0], d1[1]);
            *(float2*)(vd + 8 + (t0 + lr + 8) * VSTR) = make_float2(d1[2], d1[3]);
        }
    }
    __syncthreads();

    // ---- Phase B: 8-lane groups; coalesced hid LDG (1 inst / 4 rows) ----
    {
        const int sub = l >> 3;          // row within the warp's quad
        const int lc8 = l & 7;           // 16B chunk (4 channels)
#pragma unroll 1
        for (int r0 = w * 4; r0 < NITEM; r0 += 40) {
            const int r   = r0 + sub;    // item = tok*4 + g   (r < 320: smem-safe)
            const int tok = r >> 2, g = r & 3;
            const bool valid = (r < NITEM) && (tile_start - HALO + tok >= 0);

            float4 h4 = make_float4(0.f, 0.f, 0.f, 0.f);
            if (valid) h4 = ((const float4*)hbase)[r * 8 + lc8];

            const int c = lc8 * 4;
            ulonglong2 k2 = *(const ulonglong2*)(sm + SM_K + tok * KSTR + g * 32 + c);
            ulonglong2 n2 = *(const ulonglong2*)(sm + SM_NN + g * 32 + c);
            ulonglong2 v2 = *(const ulonglong2*)(sm + SM_V + tok * VSTR + c);
            ull hx = pack2(h4.x, h4.y), hy = pack2(h4.z, h4.w);

            ull skk2 = fma2(k2.y, k2.y, mul2(k2.x, k2.x));
            ull shh2 = fma2(hy, hy, mul2(hx, hx));
            ull skh2 = fma2(mul2(k2.y, hy), n2.y, mul2(mul2(k2.x, hx), n2.x));
            ull svv2 = fma2(v2.y, v2.y, mul2(v2.x, v2.x));

            ull s1 = pack2(lo2(skk2) + hi2(skk2), lo2(shh2) + hi2(shh2));
            ull s2 = pack2(lo2(skh2) + hi2(skh2), lo2(svv2) + hi2(svv2));
#pragma unroll
            for (int off = 1; off < 8; off <<= 1) {
                s1 = add2(s1, __shfl_xor_sync(0xffffffffu, s1, off));
                s2 = add2(s2, __shfl_xor_sync(0xffffffffu, s2, off));
            }
            if (lc8 == 0) {
                float grr = 0.f, gate = 0.f;
                if (valid) {
                    const float skk = lo2(s1), shh = hi2(s1);
                    const float skh = lo2(s2), svv = hi2(s2);
                    const float rs1 = rsqrtf(skk * (1.f/32.f) + EPSF);
                    const float rs2 = rsqrtf(shh * (1.f/32.f) + EPSF);
                    const float dot = skh * rs1 * rs2 * 0.17677669529663687f;
                    const float sq  = sqrtf(fmaxf(fabsf(dot), 1e-6f));
                    const float gs  = (dot > 0.f) ? sq : ((dot < 0.f) ? -sq : 0.f);
                    gate = 1.f / (1.f + __expf(-gs));
                    grr  = gate * rsqrtf(gate * gate * svv * (1.f/32.f) + EPSF);
                }
                if (r < NITEM) {
                    sm[SM_G + tok * 8 + g * 2 + 0] = grr;
                    sm[SM_G + tok * 8 + g * 2 + 1] = gate;
                }
            }
        }
    }
    __syncthreads();

    // ---- Phase C: conv + SiLU + residual. Warp per token, lane covers 4 ch ----
    {
        const int g    = l >> 3;
        const int c0   = (l & 7) * 4;
        const int chb  = g * 32 + c0;
        float4 cw0 = ((const float4*)cvw)[chb + 0];
        float4 cw1 = ((const float4*)cvw)[chb + 1];
        float4 cw2 = ((const float4*)cvw)[chb + 2];
        float4 cw3 = ((const float4*)cvw)[chb + 3];
        ull t9a = pack2(cw0.x, cw1.x), t9b = pack2(cw2.x, cw3.x);
        ull t6a = pack2(cw0.y, cw1.y), t6b = pack2(cw2.y, cw3.y);
        ull t3a = pack2(cw0.z, cw1.z), t3b = pack2(cw2.z, cw3.z);
        ull t0a = pack2(cw0.w, cw1.w), t0b = pack2(cw2.w, cw3.w);
        ull cna = pack2(cnw[chb], cnw[chb+1]), cnb = pack2(cnw[chb+2], cnw[chb+3]);

        for (int mt = w; mt < TILE; mt += 10) {
            const int tok = mt + HALO;
            const float* gp = sm + SM_G;
            const float grr9 = gp[(tok-9)*8 + g*2], grr6 = gp[(tok-6)*8 + g*2];
            const float grr3 = gp[(tok-3)*8 + g*2], grr0 = gp[(tok  )*8 + g*2];
            const float gate = gp[tok*8 + g*2 + 1];
            const ulonglong2 v9 = *(const ulonglong2*)&sm[SM_V + (tok-9)*VSTR + c0];
            const ulonglong2 v6 = *(const ulonglong2*)&sm[SM_V + (tok-6)*VSTR + c0];
            const ulonglong2 v3 = *(const ulonglong2*)&sm[SM_V + (tok-3)*VSTR + c0];
            const ulonglong2 v0 = *(const ulonglong2*)&sm[SM_V + (tok  )*VSTR + c0];
            const ull g92 = pack2(grr9, grr9), g62 = pack2(grr6, grr6);
            const ull g32 = pack2(grr3, grr3), g02 = pack2(grr0, grr0);
            ull ya = mul2(mul2(t9a, v9.x), g92);
            ull yb = mul2(mul2(t9b, v9.y), g92);
            ya = fma2(mul2(t6a, v6.x), g62, ya);
            yb = fma2(mul2(t6b, v6.y), g62, yb);
            ya = fma2(mul2(t3a, v3.x), g32, ya);
            yb = fma2(mul2(t3b, v3.y), g32, yb);
            ya = fma2(mul2(t0a, v0.x), g02, ya);
            yb = fma2(mul2(t0b, v0.y), g02, yb);
            ya = mul2(ya, cna);
            yb = mul2(yb, cnb);
            const float y0 = lo2(ya), y1 = hi2(ya), y2 = lo2(yb), y3 = hi2(yb);
            const float s0 = y0 / (1.f + __expf(-y0));
            const float s1 = y1 / (1.f + __expf(-y1));
            const float s2 = y2 / (1.f + __expf(-y2));
            const float s3 = y3 / (1.f + __expf(-y3));
            float4 o;
            o.x = fmaf(gate, lo2(v0.x), s0);
            o.y = fmaf(gate, hi2(v0.x), s1);
            o.z = fmaf(gate, lo2(v0.y), s2);
            o.w = fmaf(gate, hi2(v0.y), s3);
            ((float4*)out)[(((base_tok + mt) * 4 + g) * 32 + c0) >> 2] = o;
        }
    }
}

extern "C" void kernel_launch(void* const* d_in, const int* in_sizes, int n_in,
                              void* d_out, int out_size)
{
    const float* emb = (const float*)d_in[0];
    const float* hid = (const float*)d_in[1];
    const float* Wv  = (const float*)d_in[2];
    const float* bv  = (const float*)d_in[3];
    const float* Wk  = (const float*)d_in[4];
    const float* bk  = (const float*)d_in[5];
    const float* n1w = (const float*)d_in[6];
    const float* n2w = (const float*)d_in[7];
    const float* cnw = (const float*)d_in[8];
    const float* cvw = (const float*)d_in[9];
    float* out = (float*)d_out;

    const int T = 8192;
    const int B = in_sizes[0] / (T * 32);
    const size_t smem = SM_FLOATS * sizeof(float);   // 69440 B

    cudaFuncSetAttribute(engram_kernel,
                         cudaFuncAttributeMaxDynamicSharedMemorySize, (int)smem);

    dim3 grid(T / TILE, B);
    engram_kernel<<<grid, 320, smem>>>(emb, hid, Wv, bv, Wk, bk,
                                       n1w, n2w, cnw, cvw, out, T);
}